// round 2
// baseline (speedup 1.0000x reference)
#include <cuda_runtime.h>
#include <cstdint>
#include <cstddef>

// Problem constants
#define TB_   128
#define NSEQ  196
#define CDIM  512
#define HDIM  2048
#define TSTEP 4
#define BB    32
#define MROWS (TB_*NSEQ)          // 25088 (divisible by 128: 196 tiles)
#define SLAB1 (NSEQ*HDIM)         // 401408
#define SLAB2 (NSEQ*CDIM)         // 100352

// ---------------- scratch (device globals; no runtime allocation) ----------
__device__ float  g_h1[(size_t)MROWS*HDIM];   // GEMM1 output (TB,N,H)
__device__ float  g_s1[(size_t)MROWS*HDIM];   // layer-1 spikes, natural (t,b,n,h)
__device__ float  g_o2[(size_t)MROWS*CDIM];   // GEMM2 output (TB,N,C)
__device__ float  g_s2[(size_t)MROWS*CDIM];   // layer-2 spikes, natural (t,b,n,c)
__device__ double g_sum1[HDIM], g_sq1[HDIM];
__device__ double g_sum2[CDIM], g_sq2[CDIM];
__device__ float  g_mean1[HDIM], g_rstd1[HDIM];
__device__ float  g_mean2[CDIM], g_rstd2[CDIM];

// ---------------- zero the stat accumulators (per launch; graph-replayable) -
__global__ void zero_stats_kernel() {
    int i = blockIdx.x * blockDim.x + threadIdx.x;
    if (i < HDIM) { g_sum1[i] = 0.0; g_sq1[i] = 0.0; }
    if (i < CDIM) { g_sum2[i] = 0.0; g_sq2[i] = 0.0; }
}

// ---------------- SGEMM: C[M,NN] = A[M,K] * B[NN,K]^T ----------------------
// SECOND=false: A = x (row-major, lda=512), B = w1 (2048x512), C = g_h1
// SECOND=true : A = spikes with permuted addressing
//               A(r,k) = g_s1[(r/196)*401408 + k*196 + (r%196)], B = w2, C = g_o2
#define BM 128
#define BN 128
#define BK 16
#define TM 8
#define TN 8

template<bool SECOND>
__global__ __launch_bounds__(256)
void sgemm_kernel(const float* __restrict__ Ain, const float* __restrict__ B)
{
    constexpr int K  = SECOND ? HDIM : CDIM;
    constexpr int NN = SECOND ? CDIM : HDIM;
    const float* __restrict__ A = SECOND ? g_s1 : Ain;
    float* __restrict__ C = SECOND ? g_o2 : g_h1;

    __shared__ float As[BK][BM];
    __shared__ float Bs[BK][BN];

    const int tid = threadIdx.x;
    const int m0 = blockIdx.y * BM;
    const int n0 = blockIdx.x * BN;
    const int tx = tid & 15;   // 0..15  (col group of 8)
    const int ty = tid >> 4;   // 0..15  (row group of 8)

    float acc[TM][TN];
#pragma unroll
    for (int i = 0; i < TM; i++)
#pragma unroll
        for (int j = 0; j < TN; j++) acc[i][j] = 0.f;

    // Precompute permuted-A base for this thread's load row (SECOND only)
    const float* aperm_base = nullptr;
    int arow = 0;
    if (SECOND) {
        arow = tid & 127;               // 0..127 -> tile row
        int r  = m0 + arow;
        int tb = r / NSEQ;
        int n  = r - tb * NSEQ;
        aperm_base = A + (size_t)tb * SLAB1 + n;
    }

    for (int k0 = 0; k0 < K; k0 += BK) {
        // ---- load A tile into As[k][m] ----
        if (!SECOND) {
            int ar = tid >> 2;            // 0..63
            int ac = (tid & 3) * 4;       // 0,4,8,12
#pragma unroll
            for (int i = 0; i < 2; i++) {
                int row = ar + i * 64;
                float4 v = *(const float4*)(A + (size_t)(m0 + row) * K + k0 + ac);
                As[ac + 0][row] = v.x; As[ac + 1][row] = v.y;
                As[ac + 2][row] = v.z; As[ac + 3][row] = v.w;
            }
        } else {
            int kb = (tid >> 7) * 8;      // 0 or 8
#pragma unroll
            for (int j = 0; j < 8; j++) {
                As[kb + j][arow] = aperm_base[(size_t)(k0 + kb + j) * NSEQ];
            }
        }
        // ---- load B tile into Bs[k][n] (B row-major NN x K) ----
        {
            int br = tid >> 2;
            int bc = (tid & 3) * 4;
#pragma unroll
            for (int i = 0; i < 2; i++) {
                int row = br + i * 64;
                float4 v = *(const float4*)(B + (size_t)(n0 + row) * K + k0 + bc);
                Bs[bc + 0][row] = v.x; Bs[bc + 1][row] = v.y;
                Bs[bc + 2][row] = v.z; Bs[bc + 3][row] = v.w;
            }
        }
        __syncthreads();

#pragma unroll
        for (int k = 0; k < BK; k++) {
            float a[TM], b[TN];
#pragma unroll
            for (int i = 0; i < TM; i++) a[i] = As[k][ty * TM + i];
#pragma unroll
            for (int j = 0; j < TN; j++) b[j] = Bs[k][tx * TN + j];
#pragma unroll
            for (int i = 0; i < TM; i++)
#pragma unroll
                for (int j = 0; j < TN; j++)
                    acc[i][j] = fmaf(a[i], b[j], acc[i][j]);
        }
        __syncthreads();
    }

    // ---- write C ----
#pragma unroll
    for (int i = 0; i < TM; i++) {
        int r = m0 + ty * TM + i;
        float* cr = C + (size_t)r * NN + n0 + tx * TN;
#pragma unroll
        for (int j = 0; j < TN; j += 4) {
            float4 v = make_float4(acc[i][j], acc[i][j+1], acc[i][j+2], acc[i][j+3]);
            *(float4*)(cr + j) = v;
        }
    }
}

// ---------------- BN stats: per-channel sum / sumsq over 25088 rows --------
template<bool SECOND>
__global__ __launch_bounds__(256)
void bn_stats_kernel()
{
    constexpr int CH  = SECOND ? CDIM : HDIM;
    constexpr int PER = CH / 256;
    const float* __restrict__ X = SECOND ? g_o2 : g_h1;
    double* __restrict__ SUM = SECOND ? g_sum2 : g_sum1;
    double* __restrict__ SQ  = SECOND ? g_sq2  : g_sq1;

    float s[PER], q[PER];
#pragma unroll
    for (int j = 0; j < PER; j++) { s[j] = 0.f; q[j] = 0.f; }

    const int c0 = threadIdx.x;
    const float* base = X + (size_t)blockIdx.x * 128 * CH;  // 196 blocks * 128 rows
    for (int r = 0; r < 128; r++) {
        const float* row = base + (size_t)r * CH;
#pragma unroll
        for (int j = 0; j < PER; j++) {
            float v = row[c0 + j * 256];
            s[j] += v;
            q[j] = fmaf(v, v, q[j]);
        }
    }
#pragma unroll
    for (int j = 0; j < PER; j++) {
        atomicAdd(&SUM[c0 + j * 256], (double)s[j]);
        atomicAdd(&SQ[c0 + j * 256],  (double)q[j]);
    }
}

template<bool SECOND>
__global__ void bn_final_kernel()
{
    constexpr int CH = SECOND ? CDIM : HDIM;
    const double* SUM = SECOND ? g_sum2 : g_sum1;
    const double* SQ  = SECOND ? g_sq2  : g_sq1;
    float* MEAN = SECOND ? g_mean2 : g_mean1;
    float* RSTD = SECOND ? g_rstd2 : g_rstd1;
    int c = blockIdx.x * blockDim.x + threadIdx.x;
    if (c < CH) {
        const double inv_n = 1.0 / (double)MROWS;
        double m   = SUM[c] * inv_n;
        double var = SQ[c] * inv_n - m * m;
        MEAN[c] = (float)m;
        RSTD[c] = rsqrtf((float)var + 1e-5f);
    }
}

// ---------------- BN affine + 4-step LIF, emit binary spikes ---------------
// LIF: v += (x - v)/2; spike = (v >= 1); hard reset to 0.
// Forward spike is exactly heaviside ((h - sg) + sg == h in fp32 by Sterbenz).
template<bool SECOND>
__global__ __launch_bounds__(256)
void lif_kernel(const float* __restrict__ gamma, const float* __restrict__ beta)
{
    constexpr int CH   = SECOND ? CDIM : HDIM;
    constexpr int SLAB = NSEQ * CH;
    const float* __restrict__ X = SECOND ? g_o2 : g_h1;
    float* __restrict__ S = SECOND ? g_s2 : g_s1;
    const float* __restrict__ MEAN = SECOND ? g_mean2 : g_mean1;
    const float* __restrict__ RSTD = SECOND ? g_rstd2 : g_rstd1;

    size_t tid = (size_t)blockIdx.x * blockDim.x + threadIdx.x;
    int c = (int)(tid % CH);
    size_t rest = tid / CH;
    int n = (int)(rest % NSEQ);
    int b = (int)(rest / NSEQ);

    float m  = MEAN[c];
    float r  = RSTD[c];
    float gm = gamma[c];
    float bt = beta[c];

    float v = 0.f;
#pragma unroll
    for (int t = 0; t < TSTEP; t++) {
        size_t tb = (size_t)(t * BB + b);
        float x  = X[(tb * NSEQ + n) * CH + c];
        // match reference op order: gamma*(x-mean)*rstd + beta (no FMA fusion)
        float xn = __fadd_rn(__fmul_rn(__fmul_rn(gm, __fsub_rn(x, m)), r), bt);
        v = __fadd_rn(v, __fmul_rn(__fsub_rn(xn, v), 0.5f));
        float sp = (v >= 1.0f) ? 1.0f : 0.0f;
        S[tb * SLAB + (size_t)n * CH + c] = sp;
        if (v >= 1.0f) v = 0.f;   // hard reset (detached)
    }
}

// ---------------- final permuted write: out[tb][j*512+i] = s2[tb][i*196+j] -
__global__ void transpose_out_kernel(float* __restrict__ out)
{
    __shared__ float tile[32][33];
    int tb = blockIdx.z;
    int i0 = blockIdx.y * 32;   // i over 512
    int j0 = blockIdx.x * 32;   // j over 196
    const float* src = g_s2 + (size_t)tb * SLAB2;
    float* dst = out + (size_t)tb * SLAB2;
    int x = threadIdx.x, y = threadIdx.y;   // block (32,8)

#pragma unroll
    for (int yy = y; yy < 32; yy += 8) {
        int i = i0 + yy, j = j0 + x;
        if (j < NSEQ) tile[yy][x] = src[(size_t)i * NSEQ + j];
    }
    __syncthreads();
#pragma unroll
    for (int yy = y; yy < 32; yy += 8) {
        int j = j0 + yy, i = i0 + x;
        if (j < NSEQ) dst[(size_t)j * CDIM + i] = tile[x][yy];
    }
}

// ---------------- launch --------------------------------------------------
extern "C" void kernel_launch(void* const* d_in, const int* in_sizes, int n_in,
                              void* d_out, int out_size)
{
    const float* x  = (const float*)d_in[0];
    const float* w1 = (const float*)d_in[1];
    const float* g1 = (const float*)d_in[2];
    const float* b1 = (const float*)d_in[3];
    const float* w2 = (const float*)d_in[4];
    const float* g2 = (const float*)d_in[5];
    const float* b2 = (const float*)d_in[6];
    float* out = (float*)d_out;

    zero_stats_kernel<<<8, 256>>>();

    // Layer 1: x(25088x512) @ w1^T(512x2048) -> g_h1
    sgemm_kernel<false><<<dim3(HDIM / BN, MROWS / BM), 256>>>(x, w1);
    bn_stats_kernel<false><<<MROWS / 128, 256>>>();
    bn_final_kernel<false><<<HDIM / 256, 256>>>();
    lif_kernel<false><<<(BB * NSEQ * HDIM) / 256, 256>>>(g1, b1);

    // Layer 2: permuted-spikes(25088x2048) @ w2^T(2048x512) -> g_o2
    sgemm_kernel<true><<<dim3(CDIM / BN, MROWS / BM), 256>>>(nullptr, w2);
    bn_stats_kernel<true><<<MROWS / 128, 256>>>();
    bn_final_kernel<true><<<CDIM / 256, 256>>>();
    lif_kernel<true><<<(BB * NSEQ * CDIM) / 256, 256>>>(g2, b2);

    // Final flat-reshape permutation into d_out
    transpose_out_kernel<<<dim3(7, CDIM / 32, TB_), dim3(32, 8)>>>(out);
}